// round 7
// baseline (speedup 1.0000x reference)
#include <cuda_runtime.h>
#include <cuda_bf16.h>
#include <math.h>
#include <stdint.h>

#define BATCH 8
#define SEQ   1213
#define HID   768
#define NH    12
#define DH    64
#define INTER 3072
#define MROWS (BATCH*SEQ)   // 9704
#define NUM_LEAD 12
#define PATCHES 100

#define EPI_RES  1
#define EPI_GELU 2
#define EPI_F32  4
#define EPI_BF16 8

// ---------------- scratch ---------------------------------------------------------
__device__ float g_t1  [(size_t)MROWS*HID];
__device__ float g_attn[(size_t)MROWS*HID];

__device__ __nv_bfloat16 g_ah[(size_t)MROWS*INTER];
__device__ __nv_bfloat16 g_al[(size_t)MROWS*INTER];
__device__ __nv_bfloat16 g_bh[(size_t)MROWS*INTER];
__device__ __nv_bfloat16 g_bl[(size_t)MROWS*INTER];
__device__ __nv_bfloat16 g_qh[(size_t)MROWS*HID], g_ql[(size_t)MROWS*HID];
__device__ __nv_bfloat16 g_kh[(size_t)MROWS*HID], g_kl[(size_t)MROWS*HID];
__device__ __nv_bfloat16 g_vh[(size_t)MROWS*HID], g_vl[(size_t)MROWS*HID];

__device__ __nv_bfloat16 g_wqh[HID*HID],  g_wql[HID*HID];
__device__ __nv_bfloat16 g_wkh[HID*HID],  g_wkl[HID*HID];
__device__ __nv_bfloat16 g_wvh[HID*HID],  g_wvl[HID*HID];
__device__ __nv_bfloat16 g_woh[HID*HID],  g_wol[HID*HID];
__device__ __nv_bfloat16 g_wih[HID*INTER], g_wil[HID*INTER];
__device__ __nv_bfloat16 g_wdh[HID*INTER], g_wdl[HID*INTER];

// ---------------- helpers ---------------------------------------------------------
__device__ __forceinline__ float gelu_exact(float x) {
    return 0.5f * x * (1.0f + erff(x * 0.7071067811865476f));
}
__device__ __forceinline__ void ldsm4(uint32_t* r, uint32_t addr) {
    asm volatile("ldmatrix.sync.aligned.m8n8.x4.shared.b16 {%0,%1,%2,%3},[%4];\n"
                 : "=r"(r[0]), "=r"(r[1]), "=r"(r[2]), "=r"(r[3]) : "r"(addr));
}
__device__ __forceinline__ void ldsm4t(uint32_t* r, uint32_t addr) {
    asm volatile("ldmatrix.sync.aligned.m8n8.x4.trans.shared.b16 {%0,%1,%2,%3},[%4];\n"
                 : "=r"(r[0]), "=r"(r[1]), "=r"(r[2]), "=r"(r[3]) : "r"(addr));
}
__device__ __forceinline__ void mma16816(float* d, const uint32_t* a, uint32_t b0, uint32_t b1) {
    asm volatile(
        "mma.sync.aligned.m16n8k16.row.col.f32.bf16.bf16.f32 "
        "{%0,%1,%2,%3},{%4,%5,%6,%7},{%8,%9},{%0,%1,%2,%3};\n"
        : "+f"(d[0]), "+f"(d[1]), "+f"(d[2]), "+f"(d[3])
        : "r"(a[0]), "r"(a[1]), "r"(a[2]), "r"(a[3]), "r"(b0), "r"(b1));
}
__device__ __forceinline__ uint32_t packbf2(float a, float b) {
    __nv_bfloat162 h = __floats2bfloat162_rn(a, b);
    return *(uint32_t*)&h;
}
__device__ __forceinline__ void cpasync16(uint32_t saddr, const void* gaddr) {
    asm volatile("cp.async.cg.shared.global [%0], [%1], 16;" :: "r"(saddr), "l"(gaddr));
}
#define CP_COMMIT() asm volatile("cp.async.commit_group;" ::: "memory")
#define CP_WAIT2()  asm volatile("cp.async.wait_group 2;" ::: "memory")
#define CP_WAIT0()  asm volatile("cp.async.wait_group 0;" ::: "memory")

// ---------------- split / transpose-split -----------------------------------------
__global__ __launch_bounds__(256)
void split_kernel(const float* __restrict__ x, __nv_bfloat16* __restrict__ hi,
                  __nv_bfloat16* __restrict__ lo, int n4)
{
    int i = blockIdx.x * 256 + threadIdx.x;
    if (i >= n4) return;
    float4 v = ((const float4*)x)[i];
    __nv_bfloat16 h0 = __float2bfloat16(v.x), h1 = __float2bfloat16(v.y);
    __nv_bfloat16 h2 = __float2bfloat16(v.z), h3 = __float2bfloat16(v.w);
    __nv_bfloat162 hv0; hv0.x = h0; hv0.y = h1;
    __nv_bfloat162 hv1; hv1.x = h2; hv1.y = h3;
    ((__nv_bfloat162*)hi)[2*i]   = hv0;
    ((__nv_bfloat162*)hi)[2*i+1] = hv1;
    __nv_bfloat162 lv0, lv1;
    lv0.x = __float2bfloat16(v.x - __bfloat162float(h0));
    lv0.y = __float2bfloat16(v.y - __bfloat162float(h1));
    lv1.x = __float2bfloat16(v.z - __bfloat162float(h2));
    lv1.y = __float2bfloat16(v.w - __bfloat162float(h3));
    ((__nv_bfloat162*)lo)[2*i]   = lv0;
    ((__nv_bfloat162*)lo)[2*i+1] = lv1;
}

__device__ __forceinline__
void tsplit_tile(const float* __restrict__ W, __nv_bfloat16* __restrict__ Th,
                 __nv_bfloat16* __restrict__ Tl, int K, int N, int bx, int by)
{
    __shared__ float tile[32][33];
    int n0 = bx * 32, k0 = by * 32;
    int tx = threadIdx.x & 31, ty = threadIdx.x >> 5;
    #pragma unroll
    for (int r = 0; r < 4; r++)
        tile[ty + 8*r][tx] = W[(size_t)(k0 + ty + 8*r) * N + n0 + tx];
    __syncthreads();
    #pragma unroll
    for (int r = 0; r < 4; r++) {
        float v = tile[tx][ty + 8*r];
        __nv_bfloat16 h = __float2bfloat16(v);
        size_t idx = (size_t)(n0 + ty + 8*r) * K + k0 + tx;
        Th[idx] = h;
        Tl[idx] = __float2bfloat16(v - __bfloat162float(h));
    }
}

__global__ __launch_bounds__(256)
void tsplit_all(const float* Wq, const float* Wk, const float* Wv, const float* Wo,
                const float* Wi, const float* Wd,
                __nv_bfloat16* wqh, __nv_bfloat16* wql, __nv_bfloat16* wkh, __nv_bfloat16* wkl,
                __nv_bfloat16* wvh, __nv_bfloat16* wvl, __nv_bfloat16* woh, __nv_bfloat16* wol,
                __nv_bfloat16* wih, __nv_bfloat16* wil, __nv_bfloat16* wdh, __nv_bfloat16* wdl)
{
    int id = blockIdx.x;
    if (id < 2304) {
        int r = id / 576, l = id % 576;
        const float* W = (r==0)?Wq:(r==1)?Wk:(r==2)?Wv:Wo;
        __nv_bfloat16* Th = (r==0)?wqh:(r==1)?wkh:(r==2)?wvh:woh;
        __nv_bfloat16* Tl = (r==0)?wql:(r==1)?wkl:(r==2)?wvl:wol;
        tsplit_tile(W, Th, Tl, HID, HID, l % 24, l / 24);
    } else if (id < 4608) {
        int l = id - 2304;
        tsplit_tile(Wi, wih, wil, HID, INTER, l % 96, l / 96);
    } else {
        int l = id - 4608;
        tsplit_tile(Wd, wdh, wdl, INTER, HID, l % 24, l / 24);
    }
}

// ---------------- bf16x3 MMA GEMM v2: 128x128 block, 4 warps (64x64), cp.async ---
#define SA 24
#define PLANE_E (128*SA)          // 3072 elems / plane
#define STAGE_E (4*PLANE_E)       // Ah, Al, Bh, Bl
#define NSTAGE 3
#define G2_SMEM (NSTAGE*STAGE_E*2)  // 73,728 bytes

__global__ __launch_bounds__(128)
void mma_gemm(const __nv_bfloat16* __restrict__ Ah, const __nv_bfloat16* __restrict__ Al,
              const __nv_bfloat16* __restrict__ Bh, const __nv_bfloat16* __restrict__ Bl,
              const float* __restrict__ bias, const float* __restrict__ res,
              float* __restrict__ C,
              __nv_bfloat16* __restrict__ Ch, __nv_bfloat16* __restrict__ Cl,
              int M, int N, int K, int epi)
{
    extern __shared__ __nv_bfloat16 smem[];
    uint32_t sbase = (uint32_t)__cvta_generic_to_shared(smem);

    int tid = threadIdx.x, lane = tid & 31, w = tid >> 5;
    int wr = w >> 1, wc = w & 1;                 // 2x2 warp grid, 64x64 tiles
    int row0 = blockIdx.y * 128, col0 = blockIdx.x * 128;

    // ---- cp.async load mapping: 8 chunks of 16B per thread per stage ----
    // chunk i: plane = i>>1, row = (i&1)*64 + (tid>>1), half = tid&1
    int r0c = tid >> 1, half = tid & 1;
    int rA0 = row0 + r0c;        if (rA0 >= M) rA0 = M - 1;
    int rA1 = row0 + 64 + r0c;   if (rA1 >= M) rA1 = M - 1;
    int rB0 = col0 + r0c;
    int rB1 = col0 + 64 + r0c;
    const __nv_bfloat16* gp[8];
    gp[0] = Ah + (size_t)rA0 * K + half * 8;
    gp[1] = Ah + (size_t)rA1 * K + half * 8;
    gp[2] = Al + (size_t)rA0 * K + half * 8;
    gp[3] = Al + (size_t)rA1 * K + half * 8;
    gp[4] = Bh + (size_t)rB0 * K + half * 8;
    gp[5] = Bh + (size_t)rB1 * K + half * 8;
    gp[6] = Bl + (size_t)rB0 * K + half * 8;
    gp[7] = Bl + (size_t)rB1 * K + half * 8;
    uint32_t so[8];
    #pragma unroll
    for (int i = 0; i < 8; i++) {
        int plane = i >> 1;
        int rr = (i & 1) * 64 + r0c;
        so[i] = (uint32_t)(plane * PLANE_E + rr * SA + half * 8) * 2;
    }

    int NT = K / 16;

    // prologue: stages 0..2
    #pragma unroll
    for (int s = 0; s < NSTAGE; s++) {
        if (s < NT) {
            uint32_t sb = sbase + (uint32_t)s * STAGE_E * 2;
            #pragma unroll
            for (int i = 0; i < 8; i++)
                cpasync16(sb + so[i], gp[i] + (size_t)s * 16);
        }
        CP_COMMIT();
    }

    // ldmatrix per-lane offsets
    int arow_l = (lane & 7) + ((lane >> 3) & 1) * 8;
    int acol_l = (lane >> 4) * 8;
    int brow_l = (lane & 7) + ((lane >> 4) & 1) * 8;
    int bcol_l = ((lane >> 3) & 1) * 8;

    float acc[4][8][4];
    #pragma unroll
    for (int mt = 0; mt < 4; mt++)
        #pragma unroll
        for (int j = 0; j < 8; j++)
            #pragma unroll
            for (int r = 0; r < 4; r++) acc[mt][j][r] = 0.0f;

    for (int kt = 0; kt < NT; kt++) {
        CP_WAIT2();
        __syncthreads();
        uint32_t sb = sbase + (uint32_t)(kt % NSTAGE) * STAGE_E * 2;

        uint32_t aH[4][4], aL[4][4];
        #pragma unroll
        for (int mt = 0; mt < 4; mt++) {
            uint32_t rowa = wr * 64 + mt * 16 + arow_l;
            ldsm4(aH[mt], sb + (uint32_t)(0 * PLANE_E + rowa * SA + acol_l) * 2);
            ldsm4(aL[mt], sb + (uint32_t)(1 * PLANE_E + rowa * SA + acol_l) * 2);
        }
        #pragma unroll
        for (int jt = 0; jt < 4; jt++) {
            uint32_t rowb = wc * 64 + jt * 16 + brow_l;
            uint32_t bh[4], bl[4];
            ldsm4(bh, sb + (uint32_t)(2 * PLANE_E + rowb * SA + bcol_l) * 2);
            ldsm4(bl, sb + (uint32_t)(3 * PLANE_E + rowb * SA + bcol_l) * 2);
            #pragma unroll
            for (int mt = 0; mt < 4; mt++) {
                mma16816(acc[mt][2*jt],   aH[mt], bh[0], bh[1]);
                mma16816(acc[mt][2*jt+1], aH[mt], bh[2], bh[3]);
                mma16816(acc[mt][2*jt],   aH[mt], bl[0], bl[1]);
                mma16816(acc[mt][2*jt+1], aH[mt], bl[2], bl[3]);
                mma16816(acc[mt][2*jt],   aL[mt], bh[0], bh[1]);
                mma16816(acc[mt][2*jt+1], aL[mt], bh[2], bh[3]);
            }
        }

        if (kt + NSTAGE < NT) {
            __syncthreads();   // all warps done reading this buffer
            uint32_t nb = sbase + (uint32_t)(kt % NSTAGE) * STAGE_E * 2;
            #pragma unroll
            for (int i = 0; i < 8; i++)
                cpasync16(nb + so[i], gp[i] + (size_t)(kt + NSTAGE) * 16);
        }
        CP_COMMIT();
    }
    CP_WAIT0();

    // ---- epilogue ----
    #pragma unroll
    for (int mt = 0; mt < 4; mt++) {
        int r = row0 + wr * 64 + mt * 16 + (lane >> 2);
        #pragma unroll
        for (int j = 0; j < 8; j++) {
            int c = col0 + wc * 64 + 8 * j + (lane & 3) * 2;
            float2 bv = *(const float2*)&bias[c];
            float o0 = acc[mt][j][0] + bv.x, o1 = acc[mt][j][1] + bv.y;
            float o2 = acc[mt][j][2] + bv.x, o3 = acc[mt][j][3] + bv.y;
            if (epi & EPI_GELU) {
                o0 = gelu_exact(o0); o1 = gelu_exact(o1);
                o2 = gelu_exact(o2); o3 = gelu_exact(o3);
            }
            if (r < M) {
                if (epi & EPI_RES) {
                    float2 rv = *(const float2*)&res[(size_t)r*N + c];
                    o0 += rv.x; o1 += rv.y;
                }
                if (epi & EPI_F32) {
                    float2 ov; ov.x = o0; ov.y = o1;
                    *(float2*)&C[(size_t)r*N + c] = ov;
                }
                if (epi & EPI_BF16) {
                    __nv_bfloat162 hv; hv.x = __float2bfloat16(o0); hv.y = __float2bfloat16(o1);
                    *(__nv_bfloat162*)&Ch[(size_t)r*N + c] = hv;
                    __nv_bfloat162 lv;
                    lv.x = __float2bfloat16(o0 - __bfloat162float(hv.x));
                    lv.y = __float2bfloat16(o1 - __bfloat162float(hv.y));
                    *(__nv_bfloat162*)&Cl[(size_t)r*N + c] = lv;
                }
            }
            if (r + 8 < M) {
                if (epi & EPI_RES) {
                    float2 rv = *(const float2*)&res[(size_t)(r+8)*N + c];
                    o2 += rv.x; o3 += rv.y;
                }
                if (epi & EPI_F32) {
                    float2 ov; ov.x = o2; ov.y = o3;
                    *(float2*)&C[(size_t)(r+8)*N + c] = ov;
                }
                if (epi & EPI_BF16) {
                    __nv_bfloat162 hv; hv.x = __float2bfloat16(o2); hv.y = __float2bfloat16(o3);
                    *(__nv_bfloat162*)&Ch[(size_t)(r+8)*N + c] = hv;
                    __nv_bfloat162 lv;
                    lv.x = __float2bfloat16(o2 - __bfloat162float(hv.x));
                    lv.y = __float2bfloat16(o3 - __bfloat162float(hv.y));
                    *(__nv_bfloat162*)&Cl[(size_t)(r+8)*N + c] = lv;
                }
            }
        }
    }
}

// ---------------- tensor-core flash attention -------------------------------------
__device__ __forceinline__ float lead_bias(int r, int c) {
    if (r == 0) return (c >= 1 && c < NUM_LEAD + 1) ? -99999.0f : 0.0f;
    if (r <= NUM_LEAD) {
        int st = NUM_LEAD + 1 + PATCHES * (r - 1);
        return (c >= st && c < st + PATCHES) ? 0.0f : -99999.0f;
    }
    return 0.0f;
}

#define FS 72

__global__ __launch_bounds__(128)
void flash_mma(const __nv_bfloat16* __restrict__ qh, const __nv_bfloat16* __restrict__ ql,
               const __nv_bfloat16* __restrict__ kh, const __nv_bfloat16* __restrict__ kl,
               const __nv_bfloat16* __restrict__ vh,
               const float* __restrict__ amask,
               __nv_bfloat16* __restrict__ ch, __nv_bfloat16* __restrict__ cl)
{
    __shared__ __align__(16) __nv_bfloat16 sQh[64*FS], sQl[64*FS];
    __shared__ __align__(16) __nv_bfloat16 sKh[64*FS], sKl[64*FS];
    __shared__ __align__(16) __nv_bfloat16 sVh[64*FS];

    int tid = threadIdx.x, lane = tid & 31, w = tid >> 5;
    int q0 = blockIdx.x * 64;
    int h  = blockIdx.y, b = blockIdx.z;
    size_t base = (size_t)b * SEQ * HID + (size_t)h * DH;

    uint32_t uQh = (uint32_t)__cvta_generic_to_shared(sQh);
    uint32_t uQl = (uint32_t)__cvta_generic_to_shared(sQl);
    uint32_t uKh = (uint32_t)__cvta_generic_to_shared(sKh);
    uint32_t uKl = (uint32_t)__cvta_generic_to_shared(sKl);
    uint32_t uVh = (uint32_t)__cvta_generic_to_shared(sVh);

    {
        int r = tid >> 1, c0 = (tid & 1) * 32;
        int gr = q0 + r; if (gr >= SEQ) gr = SEQ - 1;
        const uint4* sh = (const uint4*)(qh + base + (size_t)gr*HID + c0);
        const uint4* sl = (const uint4*)(ql + base + (size_t)gr*HID + c0);
        uint4* dh_ = (uint4*)(sQh + r*FS + c0);
        uint4* dl_ = (uint4*)(sQl + r*FS + c0);
        #pragma unroll
        for (int i = 0; i < 4; i++) { dh_[i] = sh[i]; dl_[i] = sl[i]; }
    }

    int arow_l = (lane & 7) + ((lane >> 3) & 1) * 8;
    int acol_l = (lane >> 4) * 8;
    int brow_l = (lane & 7) + ((lane >> 4) & 1) * 8;
    int bcol_l = ((lane >> 3) & 1) * 8;
    int vmr = ((lane >> 3) & 1) * 8 + (lane & 7);
    int vmc = (lane >> 4) * 8;

    float o[8][4];
    #pragma unroll
    for (int j = 0; j < 8; j++)
        #pragma unroll
        for (int r = 0; r < 4; r++) o[j][r] = 0.0f;
    float m0 = -1e30f, m1 = -1e30f, l0 = 0.0f, l1 = 0.0f;

    int gr0 = q0 + w*16 + (lane >> 2);
    int gr1 = gr0 + 8;

    const int ntile = (SEQ + 63) / 64;
    for (int t = 0; t < ntile; t++) {
        int k0t = t * 64;
        __syncthreads();
        {
            int r = tid >> 1, c0 = (tid & 1) * 32;
            int gsr = k0t + r; if (gsr >= SEQ) gsr = SEQ - 1;
            const uint4* skh = (const uint4*)(kh + base + (size_t)gsr*HID + c0);
            const uint4* skl = (const uint4*)(kl + base + (size_t)gsr*HID + c0);
            const uint4* svh = (const uint4*)(vh + base + (size_t)gsr*HID + c0);
            uint4* dkh = (uint4*)(sKh + r*FS + c0);
            uint4* dkl = (uint4*)(sKl + r*FS + c0);
            uint4* dvh = (uint4*)(sVh + r*FS + c0);
            #pragma unroll
            for (int i = 0; i < 4; i++) { dkh[i] = skh[i]; dkl[i] = skl[i]; dvh[i] = svh[i]; }
        }
        __syncthreads();

        float s[8][4];
        #pragma unroll
        for (int j = 0; j < 8; j++)
            #pragma unroll
            for (int r = 0; r < 4; r++) s[j][r] = 0.0f;

        #pragma unroll
        for (int kk = 0; kk < 4; kk++) {
            uint32_t aqh[4], aql[4];
            ldsm4(aqh, uQh + ((w*16 + arow_l)*FS + kk*16 + acol_l)*2);
            ldsm4(aql, uQl + ((w*16 + arow_l)*FS + kk*16 + acol_l)*2);
            #pragma unroll
            for (int jj = 0; jj < 4; jj++) {
                uint32_t bh[4], bl[4];
                ldsm4(bh, uKh + ((16*jj + brow_l)*FS + kk*16 + bcol_l)*2);
                ldsm4(bl, uKl + ((16*jj + brow_l)*FS + kk*16 + bcol_l)*2);
                mma16816(s[2*jj],   aqh, bh[0], bh[1]);
                mma16816(s[2*jj+1], aqh, bh[2], bh[3]);
                mma16816(s[2*jj],   aql, bh[0], bh[1]);
                mma16816(s[2*jj+1], aql, bh[2], bh[3]);
                mma16816(s[2*jj],   aqh, bl[0], bl[1]);
                mma16816(s[2*jj+1], aqh, bl[2], bl[3]);
            }
        }

        bool lead = (q0 == 0 && w == 0);
        #pragma unroll
        for (int j = 0; j < 8; j++) {
            int c0 = k0t + j*8 + (lane & 3)*2;
            int c1 = c0 + 1;
            float am0 = (c0 < SEQ) ? amask[(size_t)b*SEQ + c0] : 0.0f;
            float am1 = (c1 < SEQ) ? amask[(size_t)b*SEQ + c1] : 0.0f;
            float v00 = s[j][0]*0.125f + am0;
            float v01 = s[j][1]*0.125f + am1;
            float v10 = s[j][2]*0.125f + am0;
            float v11 = s[j][3]*0.125f + am1;
            if (lead) {
                v00 += lead_bias(gr0, c0); v01 += lead_bias(gr0, c1);
                v10 += lead_bias(gr1, c0); v11 += lead_bias(gr1, c1);
            }
            if (c0 >= SEQ) { v00 = -1e30f; v10 = -1e30f; }
            if (c1 >= SEQ) { v01 = -1e30f; v11 = -1e30f; }
            s[j][0] = v00; s[j][1] = v01; s[j][2] = v10; s[j][3] = v11;
        }

        float mt0 = -1e30f, mt1 = -1e30f;
        #pragma unroll
        for (int j = 0; j < 8; j++) {
            mt0 = fmaxf(mt0, fmaxf(s[j][0], s[j][1]));
            mt1 = fmaxf(mt1, fmaxf(s[j][2], s[j][3]));
        }
        mt0 = fmaxf(mt0, __shfl_xor_sync(0xffffffffu, mt0, 1));
        mt0 = fmaxf(mt0, __shfl_xor_sync(0xffffffffu, mt0, 2));
        mt1 = fmaxf(mt1, __shfl_xor_sync(0xffffffffu, mt1, 1));
        mt1 = fmaxf(mt1, __shfl_xor_sync(0xffffffffu, mt1, 2));
        float mn0 = fmaxf(m0, mt0), mn1 = fmaxf(m1, mt1);
        float corr0 = __expf(m0 - mn0), corr1 = __expf(m1 - mn1);
        m0 = mn0; m1 = mn1;
        float rs0 = 0.0f, rs1 = 0.0f;
        #pragma unroll
        for (int j = 0; j < 8; j++) {
            s[j][0] = __expf(s[j][0] - mn0);
            s[j][1] = __expf(s[j][1] - mn0);
            s[j][2] = __expf(s[j][2] - mn1);
            s[j][3] = __expf(s[j][3] - mn1);
            rs0 += s[j][0] + s[j][1];
            rs1 += s[j][2] + s[j][3];
        }
        rs0 += __shfl_xor_sync(0xffffffffu, rs0, 1);
        rs0 += __shfl_xor_sync(0xffffffffu, rs0, 2);
        rs1 += __shfl_xor_sync(0xffffffffu, rs1, 1);
        rs1 += __shfl_xor_sync(0xffffffffu, rs1, 2);
        l0 = l0 * corr0 + rs0;
        l1 = l1 * corr1 + rs1;
        #pragma unroll
        for (int j = 0; j < 8; j++) {
            o[j][0] *= corr0; o[j][1] *= corr0;
            o[j][2] *= corr1; o[j][3] *= corr1;
        }

        uint32_t phA[8], phB[8], plA[8], plB[8];
        #pragma unroll
        for (int j = 0; j < 8; j++) {
            __nv_bfloat162 hA = __floats2bfloat162_rn(s[j][0], s[j][1]);
            __nv_bfloat162 hB = __floats2bfloat162_rn(s[j][2], s[j][3]);
            phA[j] = *(uint32_t*)&hA;
            phB[j] = *(uint32_t*)&hB;
            plA[j] = packbf2(s[j][0] - __bfloat162float(hA.x), s[j][1] - __bfloat162float(hA.y));
            plB[j] = packbf2(s[j][2] - __bfloat162float(hB.x), s[j][3] - __bfloat162float(hB.y));
        }

        #pragma unroll
        for (int kk = 0; kk < 4; kk++) {
            uint32_t aH[4] = { phA[2*kk], phB[2*kk], phA[2*kk+1], phB[2*kk+1] };
            uint32_t aL[4] = { plA[2*kk], plB[2*kk], plA[2*kk+1], plB[2*kk+1] };
            #pragma unroll
            for (int jj = 0; jj < 4; jj++) {
                uint32_t bv[4];
                ldsm4t(bv, uVh + ((kk*16 + vmr)*FS + jj*16 + vmc)*2);
                mma16816(o[2*jj],   aH, bv[0], bv[1]);
                mma16816(o[2*jj+1], aH, bv[2], bv[3]);
                mma16816(o[2*jj],   aL, bv[0], bv[1]);
                mma16816(o[2*jj+1], aL, bv[2], bv[3]);
            }
        }
    }

    float inv0 = 1.0f / l0, inv1 = 1.0f / l1;
    #pragma unroll
    for (int j = 0; j < 8; j++) {
        int c = j*8 + (lane & 3)*2;
        if (gr0 < SEQ) {
            float a = o[j][0]*inv0, bb = o[j][1]*inv0;
            __nv_bfloat162 hv = __floats2bfloat162_rn(a, bb);
            size_t idx = base + (size_t)gr0*HID + c;
            *(__nv_bfloat162*)&ch[idx] = hv;
            __nv_bfloat162 lv = __floats2bfloat162_rn(a - __bfloat162float(hv.x),
                                                      bb - __bfloat162float(hv.y));
            *(__nv_bfloat162*)&cl[idx] = lv;
        }
        if (gr1 < SEQ) {
            float a = o[j][2]*inv1, bb = o[j][3]*inv1;
            __nv_bfloat162 hv = __floats2bfloat162_rn(a, bb);
            size_t idx = base + (size_t)gr1*HID + c;
            *(__nv_bfloat162*)&ch[idx] = hv;
            __nv_bfloat162 lv = __floats2bfloat162_rn(a - __bfloat162float(hv.x),
                                                      bb - __bfloat162float(hv.y));
            *(__nv_bfloat162*)&cl[idx] = lv;
        }
    }
}

// ---------------- LayerNorm -------------------------------------------------------
__global__ __launch_bounds__(256)
void ln_kernel(const float* __restrict__ x, const float* __restrict__ g,
               const float* __restrict__ bta, float* __restrict__ y,
               __nv_bfloat16* __restrict__ outh, __nv_bfloat16* __restrict__ outl)
{
    __shared__ float red[8];
    int row = blockIdx.x;
    int tid = threadIdx.x;
    const float* xr = x + (size_t)row * HID;

    float v[3];
    float s = 0.0f;
    #pragma unroll
    for (int i = 0; i < 3; i++) { v[i] = xr[tid + i*256]; s += v[i]; }

    #pragma unroll
    for (int off = 16; off >= 1; off >>= 1) s += __shfl_xor_sync(0xffffffffu, s, off);
    if ((tid & 31) == 0) red[tid >> 5] = s;
    __syncthreads();
    s = red[0]+red[1]+red[2]+red[3]+red[4]+red[5]+red[6]+red[7];
    float mean = s * (1.0f / HID);
    __syncthreads();

    float s2 = 0.0f;
    #pragma unroll
    for (int i = 0; i < 3; i++) { float d = v[i] - mean; s2 += d * d; }
    #pragma unroll
    for (int off = 16; off >= 1; off >>= 1) s2 += __shfl_xor_sync(0xffffffffu, s2, off);
    if ((tid & 31) == 0) red[tid >> 5] = s2;
    __syncthreads();
    s2 = red[0]+red[1]+red[2]+red[3]+red[4]+red[5]+red[6]+red[7];
    float rstd = rsqrtf(s2 * (1.0f / HID) + 1e-12f);

    #pragma unroll
    for (int i = 0; i < 3; i++) {
        int c = tid + i*256;
        float val = g[c] * (v[i] - mean) * rstd + bta[c];
        y[(size_t)row*HID + c] = val;
        if (outh) {
            __nv_bfloat16 hv = __float2bfloat16(val);
            outh[(size_t)row*HID + c] = hv;
            outl[(size_t)row*HID + c] = __float2bfloat16(val - __bfloat162float(hv));
        }
    }
}

// ---------------- launch ----------------------------------------------------------
extern "C" void kernel_launch(void* const* d_in, const int* in_sizes, int n_in,
                              void* d_out, int out_size)
{
    const float* X     = (const float*)d_in[0];
    const float* amask = (const float*)d_in[1];
    const float* Wq = (const float*)d_in[2];  const float* bq = (const float*)d_in[3];
    const float* Wk = (const float*)d_in[4];  const float* bk = (const float*)d_in[5];
    const float* Wv = (const float*)d_in[6];  const float* bv = (const float*)d_in[7];
    const float* Wo = (const float*)d_in[8];  const float* bo = (const float*)d_in[9];
    const float* g1 = (const float*)d_in[10]; const float* b1 = (const float*)d_in[11];
    const float* Wi = (const float*)d_in[12]; const float* bi = (const float*)d_in[13];
    const float* Wd = (const float*)d_in[14]; const float* bd = (const float*)d_in[15];
    const float* g2 = (const float*)d_in[16]; const float* b2 = (const float*)d_in[17];

    float *t1, *attn;
    cudaGetSymbolAddress((void**)&t1,   g_t1);
    cudaGetSymbolAddress((void**)&attn, g_attn);

    __nv_bfloat16 *ah, *al, *bh, *bl, *qh_, *ql_, *kh_, *kl_, *vh_, *vl_;
    cudaGetSymbolAddress((void**)&ah,  g_ah);  cudaGetSymbolAddress((void**)&al,  g_al);
    cudaGetSymbolAddress((void**)&bh,  g_bh);  cudaGetSymbolAddress((void**)&bl,  g_bl);
    cudaGetSymbolAddress((void**)&qh_, g_qh);  cudaGetSymbolAddress((void**)&ql_, g_ql);
    cudaGetSymbolAddress((void**)&kh_, g_kh);  cudaGetSymbolAddress((void**)&kl_, g_kl);
    cudaGetSymbolAddress((void**)&vh_, g_vh);  cudaGetSymbolAddress((void**)&vl_, g_vl);

    __nv_bfloat16 *wqh, *wql, *wkh, *wkl, *wvh, *wvl, *woh, *wol, *wih, *wil, *wdh, *wdl;
    cudaGetSymbolAddress((void**)&wqh, g_wqh); cudaGetSymbolAddress((void**)&wql, g_wql);
    cudaGetSymbolAddress((void**)&wkh, g_wkh); cudaGetSymbolAddress((void**)&wkl, g_wkl);
    cudaGetSymbolAddress((void**)&wvh, g_wvh); cudaGetSymbolAddress((void**)&wvl, g_wvl);
    cudaGetSymbolAddress((void**)&woh, g_woh); cudaGetSymbolAddress((void**)&wol, g_wol);
    cudaGetSymbolAddress((void**)&wih, g_wih); cudaGetSymbolAddress((void**)&wil, g_wil);
    cudaGetSymbolAddress((void**)&wdh, g_wdh); cudaGetSymbolAddress((void**)&wdl, g_wdl);

    cudaFuncSetAttribute(mma_gemm, cudaFuncAttributeMaxDynamicSharedMemorySize, G2_SMEM);

    dim3 blk256(256), blk128(128);
    const int MB = (MROWS + 127) / 128;      // 76
    dim3 gGH(HID/128, MB);
    dim3 gGI(INTER/128, MB);

    tsplit_all<<<6912, blk256>>>(Wq, Wk, Wv, Wo, Wi, Wd,
                                 wqh, wql, wkh, wkl, wvh, wvl, woh, wol,
                                 wih, wil, wdh, wdl);
    int nX4 = (MROWS*HID)/4;
    split_kernel<<<(nX4 + 255)/256, blk256>>>(X, ah, al, nX4);

    mma_gemm<<<gGH, blk128, G2_SMEM>>>(ah, al, wqh, wql, bq, nullptr, nullptr, qh_, ql_, MROWS, HID, HID, EPI_BF16);
    mma_gemm<<<gGH, blk128, G2_SMEM>>>(ah, al, wkh, wkl, bk, nullptr, nullptr, kh_, kl_, MROWS, HID, HID, EPI_BF16);
    mma_gemm<<<gGH, blk128, G2_SMEM>>>(ah, al, wvh, wvl, bv, nullptr, nullptr, vh_, vl_, MROWS, HID, HID, EPI_BF16);

    dim3 gF((SEQ + 63)/64, NH, BATCH);
    flash_mma<<<gF, blk128>>>(qh_, ql_, kh_, kl_, vh_, amask, ah, al);

    mma_gemm<<<gGH, blk128, G2_SMEM>>>(ah, al, woh, wol, bo, X, t1, nullptr, nullptr, MROWS, HID, HID, EPI_RES|EPI_F32);
    ln_kernel<<<MROWS, blk256>>>(t1, g1, b1, attn, ah, al);

    mma_gemm<<<gGI, blk128, G2_SMEM>>>(ah, al, wih, wil, bi, nullptr, nullptr, bh, bl, MROWS, INTER, HID, EPI_GELU|EPI_BF16);
    mma_gemm<<<gGH, blk128, G2_SMEM>>>(bh, bl, wdh, wdl, bd, attn, t1, nullptr, nullptr, MROWS, HID, INTER, EPI_RES|EPI_F32);
    ln_kernel<<<MROWS, blk256>>>(t1, g2, b2, (float*)d_out, nullptr, nullptr);
}

// round 10
// speedup vs baseline: 1.7662x; 1.7662x over previous
#include <cuda_runtime.h>
#include <cuda_fp16.h>
#include <math.h>
#include <stdint.h>

#define BATCH 8
#define SEQ   1213
#define HID   768
#define NH    12
#define DH    64
#define INTER 3072
#define MROWS (BATCH*SEQ)   // 9704
#define NUM_LEAD 12
#define PATCHES 100

#define EPI_RES   1
#define EPI_GELU  2
#define EPI_F32   4
#define EPI_F16S  8   // fp16 hi/lo split output

// ---------------- scratch ---------------------------------------------------------
__device__ float g_t1  [(size_t)MROWS*HID];
__device__ float g_attn[(size_t)MROWS*HID];

__device__ __half g_ah[(size_t)MROWS*INTER];
__device__ __half g_al[(size_t)MROWS*INTER];
__device__ __half g_bh[(size_t)MROWS*INTER];
__device__ __half g_bl[(size_t)MROWS*INTER];
__device__ __half g_qh[(size_t)MROWS*HID], g_ql[(size_t)MROWS*HID];
__device__ __half g_kh[(size_t)MROWS*HID];
__device__ __half g_vh[(size_t)MROWS*HID];

// weights: hi plane only (B-side of every GEMM)
__device__ __half g_wq[HID*HID];
__device__ __half g_wk[HID*HID];
__device__ __half g_wv[HID*HID];
__device__ __half g_wo[HID*HID];
__device__ __half g_wi[HID*INTER];
__device__ __half g_wd[HID*INTER];

// ---------------- helpers ---------------------------------------------------------
__device__ __forceinline__ float gelu_exact(float x) {
    return 0.5f * x * (1.0f + erff(x * 0.7071067811865476f));
}
__device__ __forceinline__ void ldsm4(uint32_t* r, uint32_t addr) {
    asm volatile("ldmatrix.sync.aligned.m8n8.x4.shared.b16 {%0,%1,%2,%3},[%4];\n"
                 : "=r"(r[0]), "=r"(r[1]), "=r"(r[2]), "=r"(r[3]) : "r"(addr));
}
__device__ __forceinline__ void ldsm4t(uint32_t* r, uint32_t addr) {
    asm volatile("ldmatrix.sync.aligned.m8n8.x4.trans.shared.b16 {%0,%1,%2,%3},[%4];\n"
                 : "=r"(r[0]), "=r"(r[1]), "=r"(r[2]), "=r"(r[3]) : "r"(addr));
}
// fp16 mma, fp32 accumulate
__device__ __forceinline__ void mmah(float* d, const uint32_t* a, uint32_t b0, uint32_t b1) {
    asm volatile(
        "mma.sync.aligned.m16n8k16.row.col.f32.f16.f16.f32 "
        "{%0,%1,%2,%3},{%4,%5,%6,%7},{%8,%9},{%0,%1,%2,%3};\n"
        : "+f"(d[0]), "+f"(d[1]), "+f"(d[2]), "+f"(d[3])
        : "r"(a[0]), "r"(a[1]), "r"(a[2]), "r"(a[3]), "r"(b0), "r"(b1));
}
__device__ __forceinline__ uint32_t packh2(float a, float b) {
    __half2 h = __floats2half2_rn(a, b);
    return *(uint32_t*)&h;
}

// ---------------- split X -> fp16 hi/lo -------------------------------------------
__global__ __launch_bounds__(256)
void split_kernel(const float* __restrict__ x, __half* __restrict__ hi,
                  __half* __restrict__ lo, int n4)
{
    int i = blockIdx.x * 256 + threadIdx.x;
    if (i >= n4) return;
    float4 v = ((const float4*)x)[i];
    __half h0 = __float2half_rn(v.x), h1 = __float2half_rn(v.y);
    __half h2 = __float2half_rn(v.z), h3 = __float2half_rn(v.w);
    ((__half2*)hi)[2*i]   = __halves2half2(h0, h1);
    ((__half2*)hi)[2*i+1] = __halves2half2(h2, h3);
    __half l0 = __float2half_rn(v.x - __half2float(h0));
    __half l1 = __float2half_rn(v.y - __half2float(h1));
    __half l2 = __float2half_rn(v.z - __half2float(h2));
    __half l3 = __float2half_rn(v.w - __half2float(h3));
    ((__half2*)lo)[2*i]   = __halves2half2(l0, l1);
    ((__half2*)lo)[2*i+1] = __halves2half2(l2, l3);
}

// ---------------- all-weights transpose (hi only, ONE launch) ---------------------
__device__ __forceinline__
void tsplit_tile(const float* __restrict__ W, __half* __restrict__ Th,
                 int K, int N, int bx, int by)
{
    __shared__ float tile[32][33];
    int n0 = bx * 32, k0 = by * 32;
    int tx = threadIdx.x & 31, ty = threadIdx.x >> 5;
    #pragma unroll
    for (int r = 0; r < 4; r++)
        tile[ty + 8*r][tx] = W[(size_t)(k0 + ty + 8*r) * N + n0 + tx];
    __syncthreads();
    #pragma unroll
    for (int r = 0; r < 4; r++) {
        float v = tile[tx][ty + 8*r];
        Th[(size_t)(n0 + ty + 8*r) * K + k0 + tx] = __float2half_rn(v);
    }
}

__global__ __launch_bounds__(256)
void tsplit_all(const float* Wq, const float* Wk, const float* Wv, const float* Wo,
                const float* Wi, const float* Wd,
                __half* wq, __half* wk, __half* wv, __half* wo,
                __half* wi, __half* wd)
{
    int id = blockIdx.x;
    if (id < 2304) {
        int r = id / 576, l = id % 576;
        const float* W = (r==0)?Wq:(r==1)?Wk:(r==2)?Wv:Wo;
        __half* Th = (r==0)?wq:(r==1)?wk:(r==2)?wv:wo;
        tsplit_tile(W, Th, HID, HID, l % 24, l / 24);
    } else if (id < 4608) {
        int l = id - 2304;
        tsplit_tile(Wi, wi, HID, INTER, l % 96, l / 96);
    } else {
        int l = id - 4608;
        tsplit_tile(Wd, wd, INTER, HID, l % 24, l / 24);
    }
}

// ---------------- fp16 2-term MMA GEMM (R5 structure, 3 planes) -------------------
// C[M,N] = (Ah+Al)[M,K] * Bh[N,K]^T
#define SA 24
#define PLANE (128*SA)

__global__ __launch_bounds__(256)
void mma_gemm(const __half* __restrict__ Ah, const __half* __restrict__ Al,
              const __half* __restrict__ Bh,
              const float* __restrict__ bias, const float* __restrict__ res,
              float* __restrict__ C,
              __half* __restrict__ Ch, __half* __restrict__ Cl,
              int M, int N, int K, int epi)
{
    __shared__ __align__(16) __half sA[2*2*PLANE];   // [buf][plane: h,l]
    __shared__ __align__(16) __half sB[2*1*PLANE];   // [buf][plane: h]

    int tid = threadIdx.x, lane = tid & 31, w = tid >> 5;
    int row0 = blockIdx.y * 128, col0 = blockIdx.x * 128;
    int wm = (w >> 1) * 32, wn = (w & 1) * 64;

    int lr = tid >> 1;
    int lh = (tid & 1) * 8;
    bool avalid = (row0 + lr) < M;
    const __half* gAh = Ah + (size_t)(row0 + lr) * K + lh;
    const __half* gAl = Al + (size_t)(row0 + lr) * K + lh;
    const __half* gBh = Bh + (size_t)(col0 + lr) * K + lh;
    int st = lr * SA + lh;

    uint32_t sAu = (uint32_t)__cvta_generic_to_shared(sA);
    uint32_t sBu = (uint32_t)__cvta_generic_to_shared(sB);

    int arow_l = (lane & 7) + ((lane >> 3) & 1) * 8;
    int acol_l = (lane >> 4) * 8;
    int brow_l = (lane & 7) + ((lane >> 4) & 1) * 8;
    int bcol_l = ((lane >> 3) & 1) * 8;

    float acc[2][8][4];
    #pragma unroll
    for (int i = 0; i < 2; i++)
        #pragma unroll
        for (int j = 0; j < 8; j++)
            #pragma unroll
            for (int r = 0; r < 4; r++) acc[i][j][r] = 0.0f;

    const uint4 zero4 = make_uint4(0, 0, 0, 0);
    {
        uint4 pah = avalid ? *(const uint4*)gAh : zero4;
        uint4 pal = avalid ? *(const uint4*)gAl : zero4;
        uint4 pbh = *(const uint4*)gBh;
        *(uint4*)&sA[0*PLANE + st] = pah;
        *(uint4*)&sA[1*PLANE + st] = pal;
        *(uint4*)&sB[0*PLANE + st] = pbh;
    }
    __syncthreads();

    int NT = K / 16;
    for (int t = 0; t < NT; t++) {
        int cur = t & 1;
        uint4 pah, pal, pbh;
        if (t + 1 < NT) {
            size_t off = (size_t)(t + 1) * 16;
            pah = avalid ? *(const uint4*)(gAh + off) : zero4;
            pal = avalid ? *(const uint4*)(gAl + off) : zero4;
            pbh = *(const uint4*)(gBh + off);
        }

        uint32_t aF[2][2][4];   // [plane][mtile]
        #pragma unroll
        for (int p = 0; p < 2; p++)
            #pragma unroll
            for (int i = 0; i < 2; i++) {
                uint32_t ad = sAu + ((cur*2 + p)*PLANE + (wm + 16*i + arow_l)*SA + acol_l)*2;
                ldsm4(aF[p][i], ad);
            }

        #pragma unroll
        for (int jj = 0; jj < 4; jj++) {
            uint32_t bh[4];
            ldsm4(bh, sBu + (cur*PLANE + (wn + 16*jj + brow_l)*SA + bcol_l)*2);
            #pragma unroll
            for (int i = 0; i < 2; i++) {
                mmah(acc[i][2*jj],   aF[0][i], bh[0], bh[1]);
                mmah(acc[i][2*jj+1], aF[0][i], bh[2], bh[3]);
                mmah(acc[i][2*jj],   aF[1][i], bh[0], bh[1]);
                mmah(acc[i][2*jj+1], aF[1][i], bh[2], bh[3]);
            }
        }

        if (t + 1 < NT) {
            int nx = cur ^ 1;
            *(uint4*)&sA[(nx*2 + 0)*PLANE + st] = pah;
            *(uint4*)&sA[(nx*2 + 1)*PLANE + st] = pal;
            *(uint4*)&sB[nx*PLANE + st] = pbh;
        }
        __syncthreads();
    }

    // epilogue
    #pragma unroll
    for (int i = 0; i < 2; i++) {
        int r = row0 + wm + 16*i + (lane >> 2);
        #pragma unroll
        for (int j = 0; j < 8; j++) {
            int c = col0 + wn + 8*j + (lane & 3)*2;
            float2 bv = *(const float2*)&bias[c];
            float o0 = acc[i][j][0] + bv.x, o1 = acc[i][j][1] + bv.y;
            float o2 = acc[i][j][2] + bv.x, o3 = acc[i][j][3] + bv.y;
            if (epi & EPI_GELU) {
                o0 = gelu_exact(o0); o1 = gelu_exact(o1);
                o2 = gelu_exact(o2); o3 = gelu_exact(o3);
            }
            if (r < M) {
                if (epi & EPI_RES) {
                    float2 rv = *(const float2*)&res[(size_t)r*N + c];
                    o0 += rv.x; o1 += rv.y;
                }
                if (epi & EPI_F32) {
                    float2 ov; ov.x = o0; ov.y = o1;
                    *(float2*)&C[(size_t)r*N + c] = ov;
                }
                if (epi & EPI_F16S) {
                    __half h0 = __float2half_rn(o0), h1 = __float2half_rn(o1);
                    *(__half2*)&Ch[(size_t)r*N + c] = __halves2half2(h0, h1);
                    __half l0 = __float2half_rn(o0 - __half2float(h0));
                    __half l1 = __float2half_rn(o1 - __half2float(h1));
                    *(__half2*)&Cl[(size_t)r*N + c] = __halves2half2(l0, l1);
                }
            }
            if (r + 8 < M) {
                if (epi & EPI_RES) {
                    float2 rv = *(const float2*)&res[(size_t)(r+8)*N + c];
                    o2 += rv.x; o3 += rv.y;
                }
                if (epi & EPI_F32) {
                    float2 ov; ov.x = o2; ov.y = o3;
                    *(float2*)&C[(size_t)(r+8)*N + c] = ov;
                }
                if (epi & EPI_F16S) {
                    __half h2 = __float2half_rn(o2), h3 = __float2half_rn(o3);
                    *(__half2*)&Ch[(size_t)(r+8)*N + c] = __halves2half2(h2, h3);
                    __half l2 = __float2half_rn(o2 - __half2float(h2));
                    __half l3 = __float2half_rn(o3 - __half2float(h3));
                    *(__half2*)&Cl[(size_t)(r+8)*N + c] = __halves2half2(l2, l3);
                }
            }
        }
    }
}

// ---------------- fp16 tensor-core flash attention --------------------------------
__device__ __forceinline__ float lead_bias(int r, int c) {
    if (r == 0) return (c >= 1 && c < NUM_LEAD + 1) ? -99999.0f : 0.0f;
    if (r <= NUM_LEAD) {
        int st = NUM_LEAD + 1 + PATCHES * (r - 1);
        return (c >= st && c < st + PATCHES) ? 0.0f : -99999.0f;
    }
    return 0.0f;
}

#define FS 72

__global__ __launch_bounds__(128)
void flash_mma(const __half* __restrict__ qh, const __half* __restrict__ ql,
               const __half* __restrict__ kh,
               const __half* __restrict__ vh,
               const float* __restrict__ amask,
               __half* __restrict__ ch, __half* __restrict__ cl)
{
    __shared__ __align__(16) __half sQh[64*FS], sQl[64*FS];
    __shared__ __align__(16) __half sKh[64*FS];
    __shared__ __align__(16) __half sVh[64*FS];

    int tid = threadIdx.x, lane = tid & 31, w = tid >> 5;
    int q0 = blockIdx.x * 64;
    int h  = blockIdx.y, b = blockIdx.z;
    size_t base = (size_t)b * SEQ * HID + (size_t)h * DH;

    uint32_t uQh = (uint32_t)__cvta_generic_to_shared(sQh);
    uint32_t uQl = (uint32_t)__cvta_generic_to_shared(sQl);
    uint32_t uKh = (uint32_t)__cvta_generic_to_shared(sKh);
    uint32_t uVh = (uint32_t)__cvta_generic_to_shared(sVh);

    {
        int r = tid >> 1, c0 = (tid & 1) * 32;
        int gr = q0 + r; if (gr >= SEQ) gr = SEQ - 1;
        const uint4* sh = (const uint4*)(qh + base + (size_t)gr*HID + c0);
        const uint4* sl = (const uint4*)(ql + base + (size_t)gr*HID + c0);
        uint4* dh_ = (uint4*)(sQh + r*FS + c0);
        uint4* dl_ = (uint4*)(sQl + r*FS + c0);
        #pragma unroll
        for (int i = 0; i < 4; i++) { dh_[i] = sh[i]; dl_[i] = sl[i]; }
    }

    int arow_l = (lane & 7) + ((lane >> 3) & 1) * 8;
    int acol_l = (lane >> 4) * 8;
    int brow_l = (lane & 7) + ((lane >> 4) & 1) * 8;
    int bcol_l = ((lane >> 3) & 1) * 8;
    int vmr = ((lane >> 3) & 1) * 8 + (lane & 7);
    int vmc = (lane >> 4) * 8;

    float o[8][4];
    #pragma unroll
    for (int j = 0; j < 8; j++)
        #pragma unroll
        for (int r = 0; r < 4; r++) o[j][r] = 0.0f;
    float m0 = -1e30f, m1 = -1e30f, l0 = 0.0f, l1 = 0.0f;

    int gr0 = q0 + w*16 + (lane >> 2);
    int gr1 = gr0 + 8;

    const int ntile = (SEQ + 63) / 64;
    for (int t = 0; t < ntile; t++) {
        int k0t = t * 64;
        __syncthreads();
        {
            int r = tid >> 1, c0 = (tid & 1) * 32;
            int gsr = k0t + r; if (gsr >= SEQ) gsr = SEQ - 1;
            const uint4* skh = (const uint4*)(kh + base + (size_t)gsr*HID + c0);
            const uint4* svh = (const uint4*)(vh + base + (size_t)gsr*HID + c0);
            uint4* dkh = (uint4*)(sKh + r*FS + c0);
            uint4* dvh = (uint4*)(sVh + r*FS + c0);
            #pragma unroll
            for (int i = 0; i < 4; i++) { dkh[i] = skh[i]; dvh[i] = svh[i]; }
        }
        __syncthreads();

        // ---- S = Q K^T : (Qh+Ql) * Kh ----
        float s[8][4];
        #pragma unroll
        for (int j = 0; j < 8; j++)
            #pragma unroll
            for (int r = 0; r < 4; r++) s[j][r] = 0.0f;

        #pragma unroll
        for (int kk = 0; kk < 4; kk++) {
            uint32_t aqh[4], aql[4];
            ldsm4(aqh, uQh + ((w*16 + arow_l)*FS + kk*16 + acol_l)*2);
            ldsm4(aql, uQl + ((w*16 + arow_l)*FS + kk*16 + acol_l)*2);
            #pragma unroll
            for (int jj = 0; jj < 4; jj++) {
                uint32_t bh[4];
                ldsm4(bh, uKh + ((16*jj + brow_l)*FS + kk*16 + bcol_l)*2);
                mmah(s[2*jj],   aqh, bh[0], bh[1]);
                mmah(s[2*jj+1], aqh, bh[2], bh[3]);
                mmah(s[2*jj],   aql, bh[0], bh[1]);
                mmah(s[2*jj+1], aql, bh[2], bh[3]);
            }
        }

        bool lead = (q0 == 0 && w == 0);
        #pragma unroll
        for (int j = 0; j < 8; j++) {
            int c0 = k0t + j*8 + (lane & 3)*2;
            int c1 = c0 + 1;
            float am0 = (c0 < SEQ) ? amask[(size_t)b*SEQ + c0] : 0.0f;
            float am1 = (c1 < SEQ) ? amask[(size_t)b*SEQ + c1] : 0.0f;
            float v00 = s[j][0]*0.125f + am0;
            float v01 = s[j][1]*0.125f + am1;
            float v10 = s[j][2]*0.125f + am0;
            float v11 = s[j][3]*0.125f + am1;
            if (lead) {
                v00 += lead_bias(gr0, c0); v01 += lead_bias(gr0, c1);
                v10 += lead_bias(gr1, c0); v11 += lead_bias(gr1, c1);
            }
            if (c0 >= SEQ) { v00 = -1e30f; v10 = -1e30f; }
            if (c1 >= SEQ) { v01 = -1e30f; v11 = -1e30f; }
            s[j][0] = v00; s[j][1] = v01; s[j][2] = v10; s[j][3] = v11;
        }

        float mt0 = -1e30f, mt1 = -1e30f;
        #pragma unroll
        for (int j = 0; j < 8; j++) {
            mt0 = fmaxf(mt0, fmaxf(s[j][0], s[j][1]));
            mt1 = fmaxf(mt1, fmaxf(s[j][2], s[j][3]));
        }
        mt0 = fmaxf(mt0, __shfl_xor_sync(0xffffffffu, mt0, 1));
        mt0 = fmaxf(mt0, __shfl_xor_sync(0xffffffffu, mt0, 2));
        mt1 = fmaxf(mt1, __shfl_xor_sync(0xffffffffu, mt1, 1));
        mt1 = fmaxf(mt1, __shfl_xor_sync(0xffffffffu, mt1, 2));
        float mn0 = fmaxf(m0, mt0), mn1 = fmaxf(m1, mt1);
        float corr0 = __expf(m0 - mn0), corr1 = __expf(m1 - mn1);
        m0 = mn0; m1 = mn1;
        float rs0 = 0.0f, rs1 = 0.0f;
        #pragma unroll
        for (int j = 0; j < 8; j++) {
            s[j][0] = __expf(s[j][0] - mn0);
            s[j][1] = __expf(s[j][1] - mn0);
            s[j][2] = __expf(s[j][2] - mn1);
            s[j][3] = __expf(s[j][3] - mn1);
            rs0 += s[j][0] + s[j][1];
            rs1 += s[j][2] + s[j][3];
        }
        rs0 += __shfl_xor_sync(0xffffffffu, rs0, 1);
        rs0 += __shfl_xor_sync(0xffffffffu, rs0, 2);
        rs1 += __shfl_xor_sync(0xffffffffu, rs1, 1);
        rs1 += __shfl_xor_sync(0xffffffffu, rs1, 2);
        l0 = l0 * corr0 + rs0;
        l1 = l1 * corr1 + rs1;
        #pragma unroll
        for (int j = 0; j < 8; j++) {
            o[j][0] *= corr0; o[j][1] *= corr0;
            o[j][2] *= corr1; o[j][3] *= corr1;
        }

        // ---- pack P (fp16 hi + lo) ----
        uint32_t phA[8], phB[8], plA[8], plB[8];
        #pragma unroll
        for (int j = 0; j < 8; j++) {
            __half2 hA = __floats2half2_rn(s[j][0], s[j][1]);
            __half2 hB = __floats2half2_rn(s[j][2], s[j][3]);
            phA[j] = *(uint32_t*)&hA;
            phB[j] = *(uint32_t*)&hB;
            plA[j] = packh2(s[j][0] - __half2float(__low2half(hA)),
                            s[j][1] - __half2float(__high2half(hA)));
            plB[j] = packh2(s[j][2] - __half2float(__low2half(hB)),
                            s[j][3] - __half2float(__high2half(hB)));
        }

        // ---- O += (Ph+Pl) * Vh ----
        #pragma unroll
        for (int kk = 0; kk < 4; kk++) {
            uint32_t aH[4] = { phA[2*kk], phB[2*kk], phA[2*kk+1], phB[2*kk+1] };
            uint32_t aL[4] = { plA[2*kk], plB[2*kk], plA[2*kk+1], plB[2*kk+1] };
            #pragma unroll
            for (int jj = 0; jj < 4; jj++) {
                uint32_t bv[4];
                ldsm4t(bv, uVh + ((kk*16 + vmr)*FS + jj*16 + vmc)*2);
                mmah(o[2*jj],   aH, bv[0], bv[1]);
                mmah(o[2*jj+1], aH, bv[2], bv[3]);
                mmah(o[2*jj],   aL, bv[0], bv[1]);
                mmah(o[2*jj+1], aL, bv[2], bv[3]);
            }
        }
    }

    float inv0 = 1.0f / l0, inv1 = 1.0f / l1;
    #pragma unroll
    for (int j = 0; j < 8; j++) {
        int c = j*8 + (lane & 3)*2;
        if (gr0 < SEQ) {
            float a = o[j][0]*inv0, bb = o[j][1]*inv0;
            __half h0 = __float2half_rn(a), h1 = __float2half_rn(bb);
            size_t idx = base + (size_t)gr0*HID + c;
            *(__half2*)&ch[idx] = __halves2half2(h0, h1);
            *(__half2*)&cl[idx] = __halves2half2(
                __float2half_rn(a - __half2float(h0)),
                __float2half_rn(bb - __half2float(h1)));
        }
        if (gr1 < SEQ) {
            float a = o[j][2]*inv1, bb = o[j][3]*inv1;
            __half h0 = __float2half_rn(a), h1 = __float2half_rn(bb);
            size_t idx = base + (size_t)gr1*HID + c;
            *(__half2*)&ch[idx] = __halves2half2(h0, h1);
            *(__half2*)&cl[idx] = __halves2half2(
                __float2half_rn(a - __half2float(h0)),
                __float2half_rn(bb - __half2float(h1)));
        }
    }
}

// ---------------- LayerNorm -------------------------------------------------------
__global__ __launch_bounds__(256)
void ln_kernel(const float* __restrict__ x, const float* __restrict__ g,
               const float* __restrict__ bta, float* __restrict__ y,
               __half* __restrict__ outh, __half* __restrict__ outl)
{
    __shared__ float red[8];
    int row = blockIdx.x;
    int tid = threadIdx.x;
    const float* xr = x + (size_t)row * HID;

    float v[3];
    float s = 0.0f;
    #pragma unroll
    for (int i = 0; i < 3; i++) { v[i] = xr[tid + i*256]; s += v[i]; }

    #pragma unroll
    for (int off = 16; off >= 1; off >>= 1) s += __shfl_xor_sync(0xffffffffu, s, off);
    if ((tid & 31) == 0) red[tid >> 5] = s;
    __syncthreads();
    s = red[0]+red[1]+red[2]+red[3]+red[4]+red[5]+red[6]+red[7];
    float mean = s * (1.0f / HID);
    __syncthreads();

    float s2 = 0.0f;
    #pragma unroll
    for (int i = 0; i < 3; i++) { float d = v[i] - mean; s2 += d * d; }
    #pragma unroll
    for (int off = 16; off >= 1; off >>= 1) s2 += __shfl_xor_sync(0xffffffffu, s2, off);
    if ((tid & 31) == 0) red[tid >> 5] = s2;
    __syncthreads();
    s2 = red[0]+red[1]+red[2]+red[3]+red[4]+red[5]+red[6]+red[7];
    float rstd = rsqrtf(s2 * (1.0f / HID) + 1e-12f);

    #pragma unroll
    for (int i = 0; i < 3; i++) {
        int c = tid + i*256;
        float val = g[c] * (v[i] - mean) * rstd + bta[c];
        y[(size_t)row*HID + c] = val;
        if (outh) {
            __half hv = __float2half_rn(val);
            outh[(size_t)row*HID + c] = hv;
            outl[(size_t)row*HID + c] = __float2half_rn(val - __half2float(hv));
        }
    }
}

// ---------------- launch ----------------------------------------------------------
extern "C" void kernel_launch(void* const* d_in, const int* in_sizes, int n_in,
                              void* d_out, int out_size)
{
    const float* X     = (const float*)d_in[0];
    const float* amask = (const float*)d_in[1];
    const float* Wq = (const float*)d_in[2];  const float* bq = (const float*)d_in[3];
    const float* Wk = (const float*)d_in[4];  const float* bk = (const float*)d_in[5];
    const float* Wv = (const float*)d_in[6];  const float* bv = (const float*)d_in[7];
    const float* Wo = (const float*)d_in[8];  const float* bo = (const float*)d_in[9];
    const float* g1 = (const float*)d_in[10]; const float* b1 = (const float*)d_in[11];
    const float* Wi = (const float*)d_in[12]; const float* bi = (const float*)d_in[13];
    const float* Wd = (const float*)d_in[14]; const float* bd = (const float*)d_in[15];
    const float* g2 = (const float*)d_in[16]; const float* b2 = (const float*)d_in[17];

    float *t1, *attn;
    cudaGetSymbolAddress((void**)&t1,   g_t1);
    cudaGetSymbolAddress((void**)&attn, g_attn);

    __half *ah, *al, *bh, *bl, *qh_, *ql_, *kh_, *vh_;
    cudaGetSymbolAddress((void**)&ah,  g_ah);  cudaGetSymbolAddress((void**)&al,  g_al);
    cudaGetSymbolAddress((void**)&bh,  g_bh);  cudaGetSymbolAddress((void**)&bl,  g_bl);
    cudaGetSymbolAddress((void**)&qh_, g_qh);  cudaGetSymbolAddress((void**)&ql_, g_ql);
    cudaGetSymbolAddress((void**)&kh_, g_kh);
    cudaGetSymbolAddress((void**)&vh_, g_vh);

    __half *wq, *wk, *wv, *wo, *wi, *wd;
    cudaGetSymbolAddress((void**)&wq, g_wq);
    cudaGetSymbolAddress((void**)&wk, g_wk);
    cudaGetSymbolAddress((void**)&wv, g_wv);
    cudaGetSymbolAddress((void**)&wo, g_wo);
    cudaGetSymbolAddress((void**)&wi, g_wi);
    cudaGetSymbolAddress((void**)&wd, g_wd);

    dim3 blk256(256), blk128(128);
    const int MB = (MROWS + 127) / 128;      // 76
    dim3 gGH(HID/128, MB);
    dim3 gGI(INTER/128, MB);

    // weights: transpose to fp16 hi plane, one launch
    tsplit_all<<<6912, blk256>>>(Wq, Wk, Wv, Wo, Wi, Wd, wq, wk, wv, wo, wi, wd);
    int nX4 = (MROWS*HID)/4;
    split_kernel<<<(nX4 + 255)/256, blk256>>>(X, ah, al, nX4);

    // QKV: q needs hi+lo (A-side of S); k, v need hi only (B-side)
    mma_gemm<<<gGH, blk256>>>(ah, al, wq, bq, nullptr, nullptr, qh_, ql_, MROWS, HID, HID, EPI_F16S);
    mma_gemm<<<gGH, blk256>>>(ah, al, wk, bk, nullptr, nullptr, kh_, bl,  MROWS, HID, HID, EPI_F16S);
    mma_gemm<<<gGH, blk256>>>(ah, al, wv, bv, nullptr, nullptr, vh_, bl,  MROWS, HID, HID, EPI_F16S);

    dim3 gF((SEQ + 63)/64, NH, BATCH);
    flash_mma<<<gF, blk128>>>(qh_, ql_, kh_, vh_, amask, ah, al);

    mma_gemm<<<gGH, blk256>>>(ah, al, wo, bo, X, t1, nullptr, nullptr, MROWS, HID, HID, EPI_RES|EPI_F32);
    ln_kernel<<<MROWS, blk256>>>(t1, g1, b1, attn, ah, al);

    mma_gemm<<<gGI, blk256>>>(ah, al, wi, bi, nullptr, nullptr, bh, bl, MROWS, INTER, HID, EPI_GELU|EPI_F16S);
    mma_gemm<<<gGH, blk256>>>(bh, bl, wd, bd, attn, t1, nullptr, nullptr, MROWS, HID, INTER, EPI_RES|EPI_F32);
    ln_kernel<<<MROWS, blk256>>>(t1, g2, b2, (float*)d_out, nullptr, nullptr);
}

// round 15
// speedup vs baseline: 1.9035x; 1.0777x over previous
#include <cuda_runtime.h>
#include <cuda_fp16.h>
#include <math.h>
#include <stdint.h>

#define BATCH 8
#define SEQ   1213
#define HID   768
#define NH    12
#define DH    64
#define INTER 3072
#define MROWS (BATCH*SEQ)   // 9704
#define NUM_LEAD 12
#define PATCHES 100

#define EPI_RES   1
#define EPI_GELU  2
#define EPI_F32   4
#define EPI_F16S  8

// ---------------- scratch ---------------------------------------------------------
__device__ float g_t1  [(size_t)MROWS*HID];
__device__ float g_attn[(size_t)MROWS*HID];

__device__ __half g_ah[(size_t)MROWS*INTER];
__device__ __half g_al[(size_t)MROWS*INTER];
__device__ __half g_bh[(size_t)MROWS*INTER];
__device__ __half g_bl[(size_t)MROWS*INTER];
__device__ __half g_qh[(size_t)MROWS*HID], g_ql[(size_t)MROWS*HID];
__device__ __half g_kh[(size_t)MROWS*HID];
__device__ __half g_vh[(size_t)MROWS*HID];

__device__ __half g_wq[HID*HID];
__device__ __half g_wk[HID*HID];
__device__ __half g_wv[HID*HID];
__device__ __half g_wo[HID*HID];
__device__ __half g_wi[HID*INTER];
__device__ __half g_wd[HID*INTER];

// ---------------- helpers ---------------------------------------------------------
__device__ __forceinline__ float gelu_exact(float x) {
    return 0.5f * x * (1.0f + erff(x * 0.7071067811865476f));
}
__device__ __forceinline__ void ldsm4(uint32_t* r, uint32_t addr) {
    asm volatile("ldmatrix.sync.aligned.m8n8.x4.shared.b16 {%0,%1,%2,%3},[%4];\n"
                 : "=r"(r[0]), "=r"(r[1]), "=r"(r[2]), "=r"(r[3]) : "r"(addr));
}
__device__ __forceinline__ void ldsm4t(uint32_t* r, uint32_t addr) {
    asm volatile("ldmatrix.sync.aligned.m8n8.x4.trans.shared.b16 {%0,%1,%2,%3},[%4];\n"
                 : "=r"(r[0]), "=r"(r[1]), "=r"(r[2]), "=r"(r[3]) : "r"(addr));
}
__device__ __forceinline__ void mmah(float* d, const uint32_t* a, uint32_t b0, uint32_t b1) {
    asm volatile(
        "mma.sync.aligned.m16n8k16.row.col.f32.f16.f16.f32 "
        "{%0,%1,%2,%3},{%4,%5,%6,%7},{%8,%9},{%0,%1,%2,%3};\n"
        : "+f"(d[0]), "+f"(d[1]), "+f"(d[2]), "+f"(d[3])
        : "r"(a[0]), "r"(a[1]), "r"(a[2]), "r"(a[3]), "r"(b0), "r"(b1));
}
__device__ __forceinline__ uint32_t packh2(float a, float b) {
    __half2 h = __floats2half2_rn(a, b);
    return *(uint32_t*)&h;
}

// ---------------- split X -> fp16 hi/lo -------------------------------------------
__global__ __launch_bounds__(256)
void split_kernel(const float* __restrict__ x, __half* __restrict__ hi,
                  __half* __restrict__ lo, int n4)
{
    int i = blockIdx.x * 256 + threadIdx.x;
    if (i >= n4) return;
    float4 v = ((const float4*)x)[i];
    __half h0 = __float2half_rn(v.x), h1 = __float2half_rn(v.y);
    __half h2 = __float2half_rn(v.z), h3 = __float2half_rn(v.w);
    ((__half2*)hi)[2*i]   = __halves2half2(h0, h1);
    ((__half2*)hi)[2*i+1] = __halves2half2(h2, h3);
    __half l0 = __float2half_rn(v.x - __half2float(h0));
    __half l1 = __float2half_rn(v.y - __half2float(h1));
    __half l2 = __float2half_rn(v.z - __half2float(h2));
    __half l3 = __float2half_rn(v.w - __half2float(h3));
    ((__half2*)lo)[2*i]   = __halves2half2(l0, l1);
    ((__half2*)lo)[2*i+1] = __halves2half2(l2, l3);
}

// ---------------- all-weights transpose (hi only, ONE launch) ---------------------
__device__ __forceinline__
void tsplit_tile(const float* __restrict__ W, __half* __restrict__ Th,
                 int K, int N, int bx, int by)
{
    __shared__ float tile[32][33];
    int n0 = bx * 32, k0 = by * 32;
    int tx = threadIdx.x & 31, ty = threadIdx.x >> 5;
    #pragma unroll
    for (int r = 0; r < 4; r++)
        tile[ty + 8*r][tx] = W[(size_t)(k0 + ty + 8*r) * N + n0 + tx];
    __syncthreads();
    #pragma unroll
    for (int r = 0; r < 4; r++) {
        float v = tile[tx][ty + 8*r];
        Th[(size_t)(n0 + ty + 8*r) * K + k0 + tx] = __float2half_rn(v);
    }
}

__global__ __launch_bounds__(256)
void tsplit_all(const float* Wq, const float* Wk, const float* Wv, const float* Wo,
                const float* Wi, const float* Wd,
                __half* wq, __half* wk, __half* wv, __half* wo,
                __half* wi, __half* wd)
{
    int id = blockIdx.x;
    if (id < 2304) {
        int r = id / 576, l = id % 576;
        const float* W = (r==0)?Wq:(r==1)?Wk:(r==2)?Wv:Wo;
        __half* Th = (r==0)?wq:(r==1)?wk:(r==2)?wv:wo;
        tsplit_tile(W, Th, HID, HID, l % 24, l / 24);
    } else if (id < 4608) {
        int l = id - 2304;
        tsplit_tile(Wi, wi, HID, INTER, l % 96, l / 96);
    } else {
        int l = id - 4608;
        tsplit_tile(Wd, wd, INTER, HID, l % 24, l / 24);
    }
}

// ---------------- fp16 2-term MMA GEMM: BK=32, 2 CTAs/SM --------------------------
// C[M,N] = (Ah+Al)[M,K] * Bh[N,K]^T
#define SA2 40                       // row stride (halfs): conflict-free ldsm phases
#define PL2 (128*SA2)                // 5120 halfs / plane
#define ST2 (3*PL2)                  // Ah, Al, Bh
#define SM2 (2*ST2*2)                // 61,440 bytes (2 buffers)

__global__ __launch_bounds__(256, 2)
void mma_gemm(const __half* __restrict__ Ah, const __half* __restrict__ Al,
              const __half* __restrict__ Bh,
              const float* __restrict__ bias, const float* __restrict__ res,
              float* __restrict__ C,
              __half* __restrict__ Ch, __half* __restrict__ Cl,
              int M, int N, int K, int epi)
{
    extern __shared__ __half smem[];
    uint32_t sbase = (uint32_t)__cvta_generic_to_shared(smem);

    int tid = threadIdx.x, lane = tid & 31, w = tid >> 5;
    int row0 = blockIdx.y * 128, col0 = blockIdx.x * 128;
    int wm = (w >> 1) * 32, wn = (w & 1) * 64;

    // ---- stage-load mapping: row = tid>>2 (+64), 16B chunk = tid&3 ----
    int lr = tid >> 2, lq = tid & 3;
    int rA0 = row0 + lr;      if (rA0 >= M) rA0 = M - 1;
    int rA1 = row0 + 64 + lr; if (rA1 >= M) rA1 = M - 1;
    const __half* gp[6];
    gp[0] = Ah + (size_t)rA0 * K + lq * 8;
    gp[1] = Ah + (size_t)rA1 * K + lq * 8;
    gp[2] = Al + (size_t)rA0 * K + lq * 8;
    gp[3] = Al + (size_t)rA1 * K + lq * 8;
    gp[4] = Bh + (size_t)(col0 + lr) * K + lq * 8;
    gp[5] = Bh + (size_t)(col0 + 64 + lr) * K + lq * 8;
    uint32_t so[6];
    #pragma unroll
    for (int i = 0; i < 6; i++) {
        int plane = i >> 1;
        int rr = lr + (i & 1) * 64;
        so[i] = (uint32_t)(plane * PL2 + rr * SA2 + lq * 8) * 2;
    }

    int arow_l = (lane & 7) + ((lane >> 3) & 1) * 8;
    int acol_l = (lane >> 4) * 8;
    int brow_l = (lane & 7) + ((lane >> 4) & 1) * 8;
    int bcol_l = ((lane >> 3) & 1) * 8;

    float acc[2][8][4];
    #pragma unroll
    for (int i = 0; i < 2; i++)
        #pragma unroll
        for (int j = 0; j < 8; j++)
            #pragma unroll
            for (int r = 0; r < 4; r++) acc[i][j][r] = 0.0f;

    // prologue: stage 0 -> buffer 0
    {
        #pragma unroll
        for (int i = 0; i < 6; i++)
            *(uint4*)((char*)smem + so[i]) = *(const uint4*)gp[i];
    }
    __syncthreads();

    int NT = K / 32;
    for (int t = 0; t < NT; t++) {
        int cur = t & 1;
        uint32_t sb = sbase + (uint32_t)cur * ST2 * 2;
        uint4 pf[6];
        if (t + 1 < NT) {
            size_t off = (size_t)(t + 1) * 32;
            #pragma unroll
            for (int i = 0; i < 6; i++) pf[i] = *(const uint4*)(gp[i] + off);
        }

        #pragma unroll
        for (int kk = 0; kk < 2; kk++) {
            uint32_t co = kk * 16;
            uint32_t aF[2][2][4];
            #pragma unroll
            for (int p = 0; p < 2; p++)
                #pragma unroll
                for (int i = 0; i < 2; i++)
                    ldsm4(aF[p][i], sb + (uint32_t)(p*PL2 + (wm + 16*i + arow_l)*SA2 + co + acol_l)*2);
            #pragma unroll
            for (int jj = 0; jj < 4; jj++) {
                uint32_t bh[4];
                ldsm4(bh, sb + (uint32_t)(2*PL2 + (wn + 16*jj + brow_l)*SA2 + co + bcol_l)*2);
                #pragma unroll
                for (int i = 0; i < 2; i++) {
                    mmah(acc[i][2*jj],   aF[0][i], bh[0], bh[1]);
                    mmah(acc[i][2*jj+1], aF[0][i], bh[2], bh[3]);
                    mmah(acc[i][2*jj],   aF[1][i], bh[0], bh[1]);
                    mmah(acc[i][2*jj+1], aF[1][i], bh[2], bh[3]);
                }
            }
        }

        if (t + 1 < NT) {
            uint32_t nxoff = (uint32_t)(cur ^ 1) * ST2 * 2;
            #pragma unroll
            for (int i = 0; i < 6; i++)
                *(uint4*)((char*)smem + nxoff + so[i]) = pf[i];
        }
        __syncthreads();
    }

    // ---- epilogue ----
    #pragma unroll
    for (int i = 0; i < 2; i++) {
        int r = row0 + wm + 16*i + (lane >> 2);
        #pragma unroll
        for (int j = 0; j < 8; j++) {
            int c = col0 + wn + 8*j + (lane & 3)*2;
            float2 bv = *(const float2*)&bias[c];
            float o0 = acc[i][j][0] + bv.x, o1 = acc[i][j][1] + bv.y;
            float o2 = acc[i][j][2] + bv.x, o3 = acc[i][j][3] + bv.y;
            if (epi & EPI_GELU) {
                o0 = gelu_exact(o0); o1 = gelu_exact(o1);
                o2 = gelu_exact(o2); o3 = gelu_exact(o3);
            }
            if (r < M) {
                if (epi & EPI_RES) {
                    float2 rv = *(const float2*)&res[(size_t)r*N + c];
                    o0 += rv.x; o1 += rv.y;
                }
                if (epi & EPI_F32) {
                    float2 ov; ov.x = o0; ov.y = o1;
                    *(float2*)&C[(size_t)r*N + c] = ov;
                }
                if (epi & EPI_F16S) {
                    __half h0 = __float2half_rn(o0), h1 = __float2half_rn(o1);
                    *(__half2*)&Ch[(size_t)r*N + c] = __halves2half2(h0, h1);
                    __half l0 = __float2half_rn(o0 - __half2float(h0));
                    __half l1 = __float2half_rn(o1 - __half2float(h1));
                    *(__half2*)&Cl[(size_t)r*N + c] = __halves2half2(l0, l1);
                }
            }
            if (r + 8 < M) {
                if (epi & EPI_RES) {
                    float2 rv = *(const float2*)&res[(size_t)(r+8)*N + c];
                    o2 += rv.x; o3 += rv.y;
                }
                if (epi & EPI_F32) {
                    float2 ov; ov.x = o2; ov.y = o3;
                    *(float2*)&C[(size_t)(r+8)*N + c] = ov;
                }
                if (epi & EPI_F16S) {
                    __half h2 = __float2half_rn(o2), h3 = __float2half_rn(o3);
                    *(__half2*)&Ch[(size_t)(r+8)*N + c] = __halves2half2(h2, h3);
                    __half l2 = __float2half_rn(o2 - __half2float(h2));
                    __half l3 = __float2half_rn(o3 - __half2float(h3));
                    *(__half2*)&Cl[(size_t)(r+8)*N + c] = __halves2half2(l2, l3);
                }
            }
        }
    }
}

// ---------------- fp16 tensor-core flash attention --------------------------------
__device__ __forceinline__ float lead_bias(int r, int c) {
    if (r == 0) return (c >= 1 && c < NUM_LEAD + 1) ? -99999.0f : 0.0f;
    if (r <= NUM_LEAD) {
        int st = NUM_LEAD + 1 + PATCHES * (r - 1);
        return (c >= st && c < st + PATCHES) ? 0.0f : -99999.0f;
    }
    return 0.0f;
}

#define FS 72

__global__ __launch_bounds__(128)
void flash_mma(const __half* __restrict__ qh, const __half* __restrict__ ql,
               const __half* __restrict__ kh,
               const __half* __restrict__ vh,
               const float* __restrict__ amask,
               __half* __restrict__ ch, __half* __restrict__ cl)
{
    __shared__ __align__(16) __half sQh[64*FS], sQl[64*FS];
    __shared__ __align__(16) __half sKh[64*FS];
    __shared__ __align__(16) __half sVh[64*FS];

    int tid = threadIdx.x, lane = tid & 31, w = tid >> 5;
    int q0 = blockIdx.x * 64;
    int h  = blockIdx.y, b = blockIdx.z;
    size_t base = (size_t)b * SEQ * HID + (size_t)h * DH;

    uint32_t uQh = (uint32_t)__cvta_generic_to_shared(sQh);
    uint32_t uQl = (uint32_t)__cvta_generic_to_shared(sQl);
    uint32_t uKh = (uint32_t)__cvta_generic_to_shared(sKh);
    uint32_t uVh = (uint32_t)__cvta_generic_to_shared(sVh);

    {
        int r = tid >> 1, c0 = (tid & 1) * 32;
        int gr = q0 + r; if (gr >= SEQ) gr = SEQ - 1;
        const uint4* sh = (const uint4*)(qh + base + (size_t)gr*HID + c0);
        const uint4* sl = (const uint4*)(ql + base + (size_t)gr*HID + c0);
        uint4* dh_ = (uint4*)(sQh + r*FS + c0);
        uint4* dl_ = (uint4*)(sQl + r*FS + c0);
        #pragma unroll
        for (int i = 0; i < 4; i++) { dh_[i] = sh[i]; dl_[i] = sl[i]; }
    }

    int arow_l = (lane & 7) + ((lane >> 3) & 1) * 8;
    int acol_l = (lane >> 4) * 8;
    int brow_l = (lane & 7) + ((lane >> 4) & 1) * 8;
    int bcol_l = ((lane >> 3) & 1) * 8;
    int vmr = ((lane >> 3) & 1) * 8 + (lane & 7);
    int vmc = (lane >> 4) * 8;

    float o[8][4];
    #pragma unroll
    for (int j = 0; j < 8; j++)
        #pragma unroll
        for (int r = 0; r < 4; r++) o[j][r] = 0.0f;
    float m0 = -1e30f, m1 = -1e30f, l0 = 0.0f, l1 = 0.0f;

    int gr0 = q0 + w*16 + (lane >> 2);
    int gr1 = gr0 + 8;

    const int ntile = (SEQ + 63) / 64;
    for (int t = 0; t < ntile; t++) {
        int k0t = t * 64;
        __syncthreads();
        {
            int r = tid >> 1, c0 = (tid & 1) * 32;
            int gsr = k0t + r; if (gsr >= SEQ) gsr = SEQ - 1;
            const uint4* skh = (const uint4*)(kh + base + (size_t)gsr*HID + c0);
            const uint4* svh = (const uint4*)(vh + base + (size_t)gsr*HID + c0);
            uint4* dkh = (uint4*)(sKh + r*FS + c0);
            uint4* dvh = (uint4*)(sVh + r*FS + c0);
            #pragma unroll
            for (int i = 0; i < 4; i++) { dkh[i] = skh[i]; dvh[i] = svh[i]; }
        }
        __syncthreads();

        float s[8][4];
        #pragma unroll
        for (int j = 0; j < 8; j++)
            #pragma unroll
            for (int r = 0; r < 4; r++) s[j][r] = 0.0f;

        #pragma unroll
        for (int kk = 0; kk < 4; kk++) {
            uint32_t aqh[4], aql[4];
            ldsm4(aqh, uQh + ((w*16 + arow_l)*FS + kk*16 + acol_l)*2);
            ldsm4(aql, uQl + ((w*16 + arow_l)*FS + kk*16 + acol_l)*2);
            #pragma unroll
            for (int jj = 0; jj < 4; jj++) {
                uint32_t bh[4];
                ldsm4(bh, uKh + ((16*jj + brow_l)*FS + kk*16 + bcol_l)*2);
                mmah(s[2*jj],   aqh, bh[0], bh[1]);
                mmah(s[2*jj+1], aqh, bh[2], bh[3]);
                mmah(s[2*jj],   aql, bh[0], bh[1]);
                mmah(s[2*jj+1], aql, bh[2], bh[3]);
            }
        }

        bool lead = (q0 == 0 && w == 0);
        #pragma unroll
        for (int j = 0; j < 8; j++) {
            int c0 = k0t + j*8 + (lane & 3)*2;
            int c1 = c0 + 1;
            float am0 = (c0 < SEQ) ? amask[(size_t)b*SEQ + c0] : 0.0f;
            float am1 = (c1 < SEQ) ? amask[(size_t)b*SEQ + c1] : 0.0f;
            float v00 = s[j][0]*0.125f + am0;
            float v01 = s[j][1]*0.125f + am1;
            float v10 = s[j][2]*0.125f + am0;
            float v11 = s[j][3]*0.125f + am1;
            if (lead) {
                v00 += lead_bias(gr0, c0); v01 += lead_bias(gr0, c1);
                v10 += lead_bias(gr1, c0); v11 += lead_bias(gr1, c1);
            }
            if (c0 >= SEQ) { v00 = -1e30f; v10 = -1e30f; }
            if (c1 >= SEQ) { v01 = -1e30f; v11 = -1e30f; }
            s[j][0] = v00; s[j][1] = v01; s[j][2] = v10; s[j][3] = v11;
        }

        float mt0 = -1e30f, mt1 = -1e30f;
        #pragma unroll
        for (int j = 0; j < 8; j++) {
            mt0 = fmaxf(mt0, fmaxf(s[j][0], s[j][1]));
            mt1 = fmaxf(mt1, fmaxf(s[j][2], s[j][3]));
        }
        mt0 = fmaxf(mt0, __shfl_xor_sync(0xffffffffu, mt0, 1));
        mt0 = fmaxf(mt0, __shfl_xor_sync(0xffffffffu, mt0, 2));
        mt1 = fmaxf(mt1, __shfl_xor_sync(0xffffffffu, mt1, 1));
        mt1 = fmaxf(mt1, __shfl_xor_sync(0xffffffffu, mt1, 2));
        float mn0 = fmaxf(m0, mt0), mn1 = fmaxf(m1, mt1);
        float corr0 = __expf(m0 - mn0), corr1 = __expf(m1 - mn1);
        m0 = mn0; m1 = mn1;
        float rs0 = 0.0f, rs1 = 0.0f;
        #pragma unroll
        for (int j = 0; j < 8; j++) {
            s[j][0] = __expf(s[j][0] - mn0);
            s[j][1] = __expf(s[j][1] - mn0);
            s[j][2] = __expf(s[j][2] - mn1);
            s[j][3] = __expf(s[j][3] - mn1);
            rs0 += s[j][0] + s[j][1];
            rs1 += s[j][2] + s[j][3];
        }
        rs0 += __shfl_xor_sync(0xffffffffu, rs0, 1);
        rs0 += __shfl_xor_sync(0xffffffffu, rs0, 2);
        rs1 += __shfl_xor_sync(0xffffffffu, rs1, 1);
        rs1 += __shfl_xor_sync(0xffffffffu, rs1, 2);
        l0 = l0 * corr0 + rs0;
        l1 = l1 * corr1 + rs1;
        #pragma unroll
        for (int j = 0; j < 8; j++) {
            o[j][0] *= corr0; o[j][1] *= corr0;
            o[j][2] *= corr1; o[j][3] *= corr1;
        }

        uint32_t phA[8], phB[8], plA[8], plB[8];
        #pragma unroll
        for (int j = 0; j < 8; j++) {
            __half2 hA = __floats2half2_rn(s[j][0], s[j][1]);
            __half2 hB = __floats2half2_rn(s[j][2], s[j][3]);
            phA[j] = *(uint32_t*)&hA;
            phB[j] = *(uint32_t*)&hB;
            plA[j] = packh2(s[j][0] - __half2float(__low2half(hA)),
                            s[j][1] - __half2float(__high2half(hA)));
            plB[j] = packh2(s[j][2] - __half2float(__low2half(hB)),
                            s[j][3] - __half2float(__high2half(hB)));
        }

        #pragma unroll
        for (int kk = 0; kk < 4; kk++) {
            uint32_t aH[4] = { phA[2*kk], phB[2*kk], phA[2*kk+1], phB[2*kk+1] };
            uint32_t aL[4] = { plA[2*kk], plB[2*kk], plA[2*kk+1], plB[2*kk+1] };
            #pragma unroll
            for (int jj = 0; jj < 4; jj++) {
                uint32_t bv[4];
                ldsm4t(bv, uVh + ((kk*16 + vmr)*FS + jj*16 + vmc)*2);
                mmah(o[2*jj],   aH, bv[0], bv[1]);
                mmah(o[2*jj+1], aH, bv[2], bv[3]);
                mmah(o[2*jj],   aL, bv[0], bv[1]);
                mmah(o[2*jj+1], aL, bv[2], bv[3]);
            }
        }
    }

    float inv0 = 1.0f / l0, inv1 = 1.0f / l1;
    #pragma unroll
    for (int j = 0; j < 8; j++) {
        int c = j*8 + (lane & 3)*2;
        if (gr0 < SEQ) {
            float a = o[j][0]*inv0, bb = o[j][1]*inv0;
            __half h0 = __float2half_rn(a), h1 = __float2half_rn(bb);
            size_t idx = base + (size_t)gr0*HID + c;
            *(__half2*)&ch[idx] = __halves2half2(h0, h1);
            *(__half2*)&cl[idx] = __halves2half2(
                __float2half_rn(a - __half2float(h0)),
                __float2half_rn(bb - __half2float(h1)));
        }
        if (gr1 < SEQ) {
            float a = o[j][2]*inv1, bb = o[j][3]*inv1;
            __half h0 = __float2half_rn(a), h1 = __float2half_rn(bb);
            size_t idx = base + (size_t)gr1*HID + c;
            *(__half2*)&ch[idx] = __halves2half2(h0, h1);
            *(__half2*)&cl[idx] = __halves2half2(
                __float2half_rn(a - __half2float(h0)),
                __float2half_rn(bb - __half2float(h1)));
        }
    }
}

// ---------------- LayerNorm -------------------------------------------------------
__global__ __launch_bounds__(256)
void ln_kernel(const float* __restrict__ x, const float* __restrict__ g,
               const float* __restrict__ bta, float* __restrict__ y,
               __half* __restrict__ outh, __half* __restrict__ outl)
{
    __shared__ float red[8];
    int row = blockIdx.x;
    int tid = threadIdx.x;
    const float* xr = x + (size_t)row * HID;

    float v[3];
    float s = 0.0f;
    #pragma unroll
    for (int i = 0; i < 3; i++) { v[i] = xr[tid + i*256]; s += v[i]; }

    #pragma unroll
    for (int off = 16; off >= 1; off >>= 1) s += __shfl_xor_sync(0xffffffffu, s, off);
    if ((tid & 31) == 0) red[tid >> 5] = s;
    __syncthreads();
    s = red[0]+red[1]+red[2]+red[3]+red[4]+red[5]+red[6]+red[7];
    float mean = s * (1.0f / HID);
    __syncthreads();

    float s2 = 0.0f;
    #pragma unroll
    for (int i = 0; i < 3; i++) { float d = v[i] - mean; s2 += d * d; }
    #pragma unroll
    for (int off = 16; off >= 1; off >>= 1) s2 += __shfl_xor_sync(0xffffffffu, s2, off);
    if ((tid & 31) == 0) red[tid >> 5] = s2;
    __syncthreads();
    s2 = red[0]+red[1]+red[2]+red[3]+red[4]+red[5]+red[6]+red[7];
    float rstd = rsqrtf(s2 * (1.0f / HID) + 1e-12f);

    #pragma unroll
    for (int i = 0; i < 3; i++) {
        int c = tid + i*256;
        float val = g[c] * (v[i] - mean) * rstd + bta[c];
        y[(size_t)row*HID + c] = val;
        if (outh) {
            __half hv = __float2half_rn(val);
            outh[(size_t)row*HID + c] = hv;
            outl[(size_t)row*HID + c] = __float2half_rn(val - __half2float(hv));
        }
    }
}

// ---------------- launch ----------------------------------------------------------
extern "C" void kernel_launch(void* const* d_in, const int* in_sizes, int n_in,
                              void* d_out, int out_size)
{
    const float* X     = (const float*)d_in[0];
    const float* amask = (const float*)d_in[1];
    const float* Wq = (const float*)d_in[2];  const float* bq = (const float*)d_in[3];
    const float* Wk = (const float*)d_in[4];  const float* bk = (const float*)d_in[5];
    const float* Wv = (const float*)d_in[6];  const float* bv = (const float*)d_in[7];
    const float* Wo = (const float*)d_in[8];  const float* bo = (const float*)d_in[9];
    const float* g1 = (const float*)d_in[10]; const float* b1 = (const float*)d_in[11];
    const float* Wi = (const float*)d_in[12]; const float* bi = (const float*)d_in[13];
    const float* Wd = (const float*)d_in[14]; const float* bd = (const float*)d_in[15];
    const float* g2 = (const float*)d_in[16]; const float* b2 = (const float*)d_in[17];

    float *t1, *attn;
    cudaGetSymbolAddress((void**)&t1,   g_t1);
    cudaGetSymbolAddress((void**)&attn, g_attn);

    __half *ah, *al, *bh, *bl, *qh_, *ql_, *kh_, *vh_;
    cudaGetSymbolAddress((void**)&ah,  g_ah);  cudaGetSymbolAddress((void**)&al,  g_al);
    cudaGetSymbolAddress((void**)&bh,  g_bh);  cudaGetSymbolAddress((void**)&bl,  g_bl);
    cudaGetSymbolAddress((void**)&qh_, g_qh);  cudaGetSymbolAddress((void**)&ql_, g_ql);
    cudaGetSymbolAddress((void**)&kh_, g_kh);
    cudaGetSymbolAddress((void**)&vh_, g_vh);

    __half *wq, *wk, *wv, *wo, *wi, *wd;
    cudaGetSymbolAddress((void**)&wq, g_wq);
    cudaGetSymbolAddress((void**)&wk, g_wk);
    cudaGetSymbolAddress((void**)&wv, g_wv);
    cudaGetSymbolAddress((void**)&wo, g_wo);
    cudaGetSymbolAddress((void**)&wi, g_wi);
    cudaGetSymbolAddress((void**)&wd, g_wd);

    cudaFuncSetAttribute(mma_gemm, cudaFuncAttributeMaxDynamicSharedMemorySize, SM2);

    dim3 blk256(256), blk128(128);
    const int MB = (MROWS + 127) / 128;      // 76
    dim3 gGH(HID/128, MB);
    dim3 gGI(INTER/128, MB);

    tsplit_all<<<6912, blk256>>>(Wq, Wk, Wv, Wo, Wi, Wd, wq, wk, wv, wo, wi, wd);
    int nX4 = (MROWS*HID)/4;
    split_kernel<<<(nX4 + 255)/256, blk256>>>(X, ah, al, nX4);

    mma_gemm<<<gGH, blk256, SM2>>>(ah, al, wq, bq, nullptr, nullptr, qh_, ql_, MROWS, HID, HID, EPI_F16S);
    mma_gemm<<<gGH, blk256, SM2>>>(ah, al, wk, bk, nullptr, nullptr, kh_, bl,  MROWS, HID, HID, EPI_F16S);
    mma_gemm<<<gGH, blk256, SM2>>>(ah, al, wv, bv, nullptr, nullptr, vh_, bl,  MROWS, HID, HID, EPI_F16S);

    dim3 gF((SEQ + 63)/64, NH, BATCH);
    flash_mma<<<gF, blk128>>>(qh_, ql_, kh_, vh_, amask, ah, al);

    mma_gemm<<<gGH, blk256, SM2>>>(ah, al, wo, bo, X, t1, nullptr, nullptr, MROWS, HID, HID, EPI_RES|EPI_F32);
    ln_kernel<<<MROWS, blk256>>>(t1, g1, b1, attn, ah, al);

    mma_gemm<<<gGI, blk256, SM2>>>(ah, al, wi, bi, nullptr, nullptr, bh, bl, MROWS, INTER, HID, EPI_GELU|EPI_F16S);
    mma_gemm<<<gGH, blk256, SM2>>>(bh, bl, wd, bd, attn, t1, nullptr, nullptr, MROWS, HID, INTER, EPI_RES|EPI_F32);
    ln_kernel<<<MROWS, blk256>>>(t1, g2, b2, (float*)d_out, nullptr, nullptr);
}